// round 6
// baseline (speedup 1.0000x reference)
#include <cuda_runtime.h>
#include <cuda_bf16.h>
#include <cstdint>

#define N_TOKENS  131072
#define NUM_CODES 1024
#define CODE_DIM  64
#define DECAY     0.99f
#define OMD       0.01f
#define EPS       1e-5f

#define OUT_Q     0
#define OUT_IDX   (N_TOKENS * CODE_DIM)
#define OUT_LOSS  (OUT_IDX + N_TOKENS)
#define OUT_CB    (OUT_LOSS + 1)
#define OUT_CS    (OUT_CB + NUM_CODES * CODE_DIM)
#define OUT_EMA   (OUT_CS + NUM_CODES)

#define MARGIN 2.0f
#define CAP    8
#define NCHUNK 16

// dynamic smem layout (bytes)
#define SM_AS    0
#define SM_BS    36864            // 256*144
#define SM_CNS   (SM_BS + 16 * 64 * 144)   // 184320
#define SM_THR   (SM_CNS + 4096)  // 188416
#define SM_CNT   (SM_THR + 1024)  // 189440
#define SM_CAND  (SM_CNT + 1024)  // 190464
#define SMEM_BYTES (SM_CAND + 256 * CAP * 2)  // 194560

// ---------------- device scratch ----------------
__device__ __align__(16) __nv_bfloat16 g_cbh[NUM_CODES * CODE_DIM];
__device__ float g_dw[NUM_CODES * CODE_DIM];
__device__ float g_counts[NUM_CODES];
__device__ float g_cnorm[NUM_CODES];
__device__ float g_inv[NUM_CODES];
__device__ float g_loss;

// ---------------- helpers ----------------
__device__ __forceinline__ uint32_t smem_u32(const void* p) {
    uint32_t a;
    asm("{ .reg .u64 t; cvta.to.shared.u64 t, %1; cvt.u32.u64 %0, t; }" : "=r"(a) : "l"(p));
    return a;
}
__device__ __forceinline__ void ldsm_x4(uint32_t& r0, uint32_t& r1, uint32_t& r2,
                                        uint32_t& r3, uint32_t addr) {
    asm volatile("ldmatrix.sync.aligned.m8n8.x4.shared.b16 {%0,%1,%2,%3}, [%4];"
                 : "=r"(r0), "=r"(r1), "=r"(r2), "=r"(r3) : "r"(addr));
}
__device__ __forceinline__ void mma16816(float* c, const uint32_t* a,
                                         uint32_t b0, uint32_t b1) {
    asm volatile(
        "mma.sync.aligned.m16n8k16.row.col.f32.bf16.bf16.f32 "
        "{%0,%1,%2,%3}, {%4,%5,%6,%7}, {%8,%9}, {%0,%1,%2,%3};"
        : "+f"(c[0]), "+f"(c[1]), "+f"(c[2]), "+f"(c[3])
        : "r"(a[0]), "r"(a[1]), "r"(a[2]), "r"(a[3]), "r"(b0), "r"(b1));
}
__device__ __forceinline__ unsigned bf2u(float a, float b) {
    __nv_bfloat162 p(__float2bfloat16_rn(a), __float2bfloat16_rn(b));
    return *(unsigned*)&p;
}

// ---------------- prep kernels (split so assign lands at launch position 3) ----------------
__global__ void prep_zero_a_kernel() {
    int i = blockIdx.x * 256 + threadIdx.x;   // 8192 threads -> lower half of g_dw
    ((float4*)g_dw)[i] = make_float4(0.f, 0.f, 0.f, 0.f);
    if (i < NUM_CODES) g_counts[i] = 0.0f;
}

__global__ void prep_cb_kernel(const float4* __restrict__ cb4) {
    int i = blockIdx.x * 256 + threadIdx.x;   // 16384 threads
    float4 v = cb4[i];
    uint2 o;
    o.x = bf2u(v.x, v.y);
    o.y = bf2u(v.z, v.w);
    ((uint2*)g_cbh)[i] = o;
    if (i < NUM_CODES) {
        float s = 0.0f;
        const float4* c = cb4 + i * 16;
#pragma unroll
        for (int j = 0; j < 16; j++) {
            float4 w = c[j];
            s += w.x * w.x + w.y * w.y + w.z * w.z + w.w * w.w;
        }
        g_cnorm[i] = s;
    }
}

__global__ void prep_zero_b_kernel() {
    int i = blockIdx.x * 256 + threadIdx.x;   // 8192 threads -> upper half of g_dw
    ((float4*)g_dw)[8192 + i] = make_float4(0.f, 0.f, 0.f, 0.f);
    if (i == 0) g_loss = 0.0f;
}

// ---------------- assign: two-pass bf16 MMA + exact rescore ----------------
// 256 threads (8 warps), 256 tokens/CTA, 512 CTAs. Full codebook resident in smem.
__global__ void __launch_bounds__(256)
assign_kernel(const float4* __restrict__ z4, const float4* __restrict__ cb4,
              float* __restrict__ out) {
    extern __shared__ __align__(16) unsigned char smem[];
    float*          cns_s  = (float*)(smem + SM_CNS);
    float*          thr_s  = (float*)(smem + SM_THR);
    unsigned*       cnt    = (unsigned*)(smem + SM_CNT);
    unsigned short* cand   = (unsigned short*)(smem + SM_CAND);

    const int tid  = threadIdx.x;
    const int w    = tid >> 5;
    const int lane = tid & 31;
    const int base = blockIdx.x * 256;
    const uint32_t AsA = smem_u32(smem + SM_AS);
    const uint32_t BsA = smem_u32(smem + SM_BS);

    cnt[tid] = 0u;

    // ---- stage z tile: fp32 -> bf16, 256 rows x 128B (stride 144)
#pragma unroll
    for (int i = 0; i < 16; i++) {
        int l = tid + i * 256;                 // 4096 float4
        int row = l >> 4, j = l & 15;
        float4 v = z4[(size_t)(base + row) * 16 + j];
        uint2 o; o.x = bf2u(v.x, v.y); o.y = bf2u(v.z, v.w);
        *(uint2*)(smem + SM_AS + row * 144 + j * 8) = o;
    }

    // ---- stage FULL bf16 codebook: 16 chunks x 64 rows x 128B (stride 144)
    {
        const uint4* src = (const uint4*)g_cbh;
#pragma unroll
        for (int i = 0; i < 32; i++) {
            int l = tid + i * 256;             // 8192 uint4
            int chunk = l >> 9, rem = l & 511;
            int row = rem >> 3, j = rem & 7;
            *(uint4*)(smem + SM_BS + chunk * 9216 + row * 144 + j * 16) =
                src[(chunk * 64 + row) * 8 + j];
        }
    }
#pragma unroll
    for (int i = 0; i < 4; i++) cns_s[tid + i * 256] = g_cnorm[tid + i * 256];

    __syncthreads();

    // ---- load A fragments once: af[mt][ks][4]
    uint32_t af[2][4][4];
#pragma unroll
    for (int mt = 0; mt < 2; mt++) {
#pragma unroll
        for (int ks = 0; ks < 4; ks++) {
            uint32_t addr = AsA + (w * 32 + mt * 16 + (lane & 15)) * 144
                          + ((lane >> 4) << 4) + ks * 32;
            ldsm_x4(af[mt][ks][0], af[mt][ks][1], af[mt][ks][2], af[mt][ks][3], addr);
        }
    }

    // ================= PASS 1: approx min (register-only) =================
    float rb[4];
#pragma unroll
    for (int i = 0; i < 4; i++) rb[i] = 3.0e38f;

    for (int c = 0; c < NCHUNK; c++) {
#pragma unroll
        for (int nt = 0; nt < 8; nt++) {
            uint32_t b[8];
            uint32_t baddr = BsA + c * 9216 + (nt * 8 + (lane & 7)) * 144
                           + ((lane >> 3) << 4);
            ldsm_x4(b[0], b[1], b[2], b[3], baddr);
            ldsm_x4(b[4], b[5], b[6], b[7], baddr + 64);

            float acc[2][4];
#pragma unroll
            for (int mt = 0; mt < 2; mt++) {
                acc[mt][0] = acc[mt][1] = acc[mt][2] = acc[mt][3] = 0.0f;
                mma16816(acc[mt], af[mt][0], b[0], b[1]);
                mma16816(acc[mt], af[mt][1], b[2], b[3]);
                mma16816(acc[mt], af[mt][2], b[4], b[5]);
                mma16816(acc[mt], af[mt][3], b[6], b[7]);
            }
            float2 cnv = *(const float2*)&cns_s[c * 64 + nt * 8 + 2 * (lane & 3)];
#pragma unroll
            for (int mt = 0; mt < 2; mt++) {
#pragma unroll
                for (int ap = 0; ap < 2; ap++) {
                    float s0 = fmaf(-2.0f, acc[mt][ap * 2 + 0], cnv.x);
                    float s1 = fmaf(-2.0f, acc[mt][ap * 2 + 1], cnv.y);
                    rb[mt * 2 + ap] = fminf(rb[mt * 2 + ap], fminf(s0, s1));
                }
            }
        }
    }
    // reduce across the 4 lanes holding the same row; publish final thresholds
#pragma unroll
    for (int i = 0; i < 4; i++) {
        rb[i] = fminf(rb[i], __shfl_xor_sync(0xffffffffu, rb[i], 1));
        rb[i] = fminf(rb[i], __shfl_xor_sync(0xffffffffu, rb[i], 2));
    }
    if ((lane & 3) == 0) {
#pragma unroll
        for (int mt = 0; mt < 2; mt++)
#pragma unroll
            for (int ap = 0; ap < 2; ap++)
                thr_s[w * 32 + mt * 16 + (lane >> 2) + 8 * ap] =
                    rb[mt * 2 + ap] + MARGIN;
    }
    __syncthreads();

    // ================= PASS 2: candidate collection vs final threshold =================
    float thrv[4];
#pragma unroll
    for (int mt = 0; mt < 2; mt++)
#pragma unroll
        for (int ap = 0; ap < 2; ap++)
            thrv[mt * 2 + ap] = thr_s[w * 32 + mt * 16 + (lane >> 2) + 8 * ap];

    for (int c = 0; c < NCHUNK; c++) {
        const int kb = c * 64;
#pragma unroll
        for (int nt = 0; nt < 8; nt++) {
            uint32_t b[8];
            uint32_t baddr = BsA + c * 9216 + (nt * 8 + (lane & 7)) * 144
                           + ((lane >> 3) << 4);
            ldsm_x4(b[0], b[1], b[2], b[3], baddr);
            ldsm_x4(b[4], b[5], b[6], b[7], baddr + 64);

            float acc[2][4];
#pragma unroll
            for (int mt = 0; mt < 2; mt++) {
                acc[mt][0] = acc[mt][1] = acc[mt][2] = acc[mt][3] = 0.0f;
                mma16816(acc[mt], af[mt][0], b[0], b[1]);
                mma16816(acc[mt], af[mt][1], b[2], b[3]);
                mma16816(acc[mt], af[mt][2], b[4], b[5]);
                mma16816(acc[mt], af[mt][3], b[6], b[7]);
            }
            float2 cnv = *(const float2*)&cns_s[c * 64 + nt * 8 + 2 * (lane & 3)];
#pragma unroll
            for (int mt = 0; mt < 2; mt++) {
#pragma unroll
                for (int ap = 0; ap < 2; ap++) {
                    float s0 = fmaf(-2.0f, acc[mt][ap * 2 + 0], cnv.x);
                    float s1 = fmaf(-2.0f, acc[mt][ap * 2 + 1], cnv.y);
                    float t = thrv[mt * 2 + ap];
                    int tok_l = w * 32 + mt * 16 + (lane >> 2) + 8 * ap;
                    if (s0 <= t) {
                        unsigned slot = atomicAdd(&cnt[tok_l], 1u);
                        if (slot < CAP)
                            cand[tok_l * CAP + slot] =
                                (unsigned short)(kb + nt * 8 + 2 * (lane & 3));
                    }
                    if (s1 <= t) {
                        unsigned slot = atomicAdd(&cnt[tok_l], 1u);
                        if (slot < CAP)
                            cand[tok_l * CAP + slot] =
                                (unsigned short)(kb + nt * 8 + 2 * (lane & 3) + 1);
                    }
                }
            }
        }
    }
    __syncthreads();

    // ================= Phase B: exact fp32 rescore + outputs + scatter =================
    const int tok = base + tid;
    const float4* zsrc = z4 + (size_t)tok * 16;

    float zn = 0.0f;
#pragma unroll
    for (int j = 0; j < 16; j++) {
        float4 v = zsrc[j];
        zn += v.x * v.x + v.y * v.y + v.z * v.z + v.w * v.w;
    }

    float best = 3.0e38f;
    int   bk   = 0;
    unsigned n = cnt[tid];
    if (n > 0 && n <= CAP) {
        for (unsigned u = 0; u < n; u++) {
            int k = cand[tid * CAP + u];
            const float4* cr = cb4 + (size_t)k * 16;
            float dot = 0.0f;
#pragma unroll
            for (int j = 0; j < 16; j++) {
                float4 a = zsrc[j];
                float4 v = cr[j];
                dot += a.x * v.x + a.y * v.y + a.z * v.z + a.w * v.w;
            }
            float s = fmaf(-2.0f, dot, g_cnorm[k]);
            if (s < best || (s == best && k < bk)) { best = s; bk = k; }
        }
    } else {
        for (int k = 0; k < NUM_CODES; k++) {
            const float4* cr = cb4 + (size_t)k * 16;
            float dot = 0.0f;
#pragma unroll
            for (int j = 0; j < 16; j++) {
                float4 a = zsrc[j];
                float4 v = cr[j];
                dot += a.x * v.x + a.y * v.y + a.z * v.z + a.w * v.w;
            }
            float s = fmaf(-2.0f, dot, g_cnorm[k]);
            if (s < best) { best = s; bk = k; }
        }
    }

    out[OUT_IDX + tok] = (float)bk;
    atomicAdd(&g_counts[bk], 1.0f);
    float4* outq = (float4*)out;   // OUT_Q == 0
    const float4* cbest = cb4 + (size_t)bk * 16;
    float* dwp = &g_dw[bk * 64];
#pragma unroll
    for (int j = 0; j < 16; j++) {
        float4 a = zsrc[j];
        outq[(size_t)tok * 16 + j] = cbest[j];
        atomicAdd(&dwp[4 * j + 0], a.x);
        atomicAdd(&dwp[4 * j + 1], a.y);
        atomicAdd(&dwp[4 * j + 2], a.z);
        atomicAdd(&dwp[4 * j + 3], a.w);
    }

    float lp = zn + best;   // exact d2min
#pragma unroll
    for (int off = 16; off > 0; off >>= 1)
        lp += __shfl_down_sync(0xffffffffu, lp, off);
    if (lane == 0) atomicAdd(&g_loss, lp);
}

// ---------------- finalize A: per-code stats + loss ----------------
__global__ void finalize_a_kernel(const float* __restrict__ cs_in,
                                  float* __restrict__ out) {
    __shared__ float s[1024];
    int k = threadIdx.x;
    float ncs = DECAY * cs_in[k] + OMD * g_counts[k];
    s[k] = ncs;
    __syncthreads();
    for (int st = 512; st > 0; st >>= 1) {
        if (k < st) s[k] += s[k + st];
        __syncthreads();
    }
    float n   = s[0];
    float csk = (ncs + EPS) / (n + NUM_CODES * EPS) * n;
    out[OUT_CS + k] = ncs;
    g_inv[k] = 1.0f / csk;
    if (k == 0) out[OUT_LOSS] = g_loss * (1.0f / (float)(N_TOKENS * CODE_DIM));
}

// ---------------- finalize B: parallel EMA + codebook update ----------------
__global__ void finalize_b_kernel(const float* __restrict__ ema_in,
                                  float* __restrict__ out) {
    int i = blockIdx.x * 256 + threadIdx.x;   // 65536 threads
    float e = DECAY * ema_in[i] + OMD * g_dw[i];
    out[OUT_EMA + i] = e;
    out[OUT_CB + i]  = e * g_inv[i >> 6];
}

extern "C" void kernel_launch(void* const* d_in, const int* in_sizes, int n_in,
                              void* d_out, int out_size) {
    const float* z   = (const float*)d_in[0];
    const float* cb  = (const float*)d_in[1];
    const float* cs  = (const float*)d_in[2];
    const float* ema = (const float*)d_in[3];
    float* out = (float*)d_out;

    static int smem_set = 0;
    if (!smem_set) {
        cudaFuncSetAttribute(assign_kernel,
                             cudaFuncAttributeMaxDynamicSharedMemorySize, SMEM_BYTES);
        smem_set = 1;
    }

    prep_zero_a_kernel<<<32, 256>>>();                                   // pos 0
    prep_cb_kernel<<<64, 256>>>((const float4*)cb);                      // pos 1
    prep_zero_b_kernel<<<32, 256>>>();                                   // pos 2
    assign_kernel<<<512, 256, SMEM_BYTES>>>((const float4*)z,            // pos 3
                                            (const float4*)cb, out);
    finalize_a_kernel<<<1, 1024>>>(cs, out);                             // pos 4
    finalize_b_kernel<<<256, 256>>>(ema, out);                           // pos 5
}

// round 9
// speedup vs baseline: 1.6435x; 1.6435x over previous
#include <cuda_runtime.h>
#include <cstdint>

typedef unsigned long long u64;

#define N_TOKENS  131072
#define NUM_CODES 1024
#define CODE_DIM  64
#define DECAY     0.99f
#define OMD       0.01f
#define EPS       1e-5f

#define OUT_Q     0
#define OUT_IDX   (N_TOKENS * CODE_DIM)
#define OUT_LOSS  (OUT_IDX + N_TOKENS)
#define OUT_CB    (OUT_LOSS + 1)
#define OUT_CS    (OUT_CB + NUM_CODES * CODE_DIM)
#define OUT_EMA   (OUT_CS + NUM_CODES)

// smem layout (bytes) — ALL row strides multiples of 16
#define ZSTRIDE   1040                     // 65 * 16
#define SM_Z      0                        // 64 rows x 1040 B = 66560 (dup z pairs)
#define SM_C      66560                    // 64 rows x 272 B  = 17408 (code pairs, padded)
#define SM_CNS    (66560 + 17408)          // 83968: 1024 floats = 4096
#define SM_SIDX   88064                    // 128 int = 512
#define SM_SBEST  88576                    // 128 float = 512
#define SMEM_BYTES 89088

// ---------------- device scratch ----------------
__device__ __align__(16) u64 g_cbp[16 * 64 * 32];  // [chunk][dim][pair] packed code pairs
__device__ float g_dw[NUM_CODES * CODE_DIM];
__device__ float g_counts[NUM_CODES];
__device__ float g_cnorm[NUM_CODES];
__device__ float g_inv[NUM_CODES];
__device__ float g_loss;

// ---------------- f32x2 helpers ----------------
__device__ __forceinline__ u64 pk2(float x, float y) {
    u64 r; asm("mov.b64 %0, {%1, %2};" : "=l"(r) : "f"(x), "f"(y)); return r;
}
__device__ __forceinline__ void upk2(u64 v, float& x, float& y) {
    asm("mov.b64 {%0, %1}, %2;" : "=f"(x), "=f"(y) : "l"(v));
}
__device__ __forceinline__ u64 fma2(u64 a, u64 b, u64 c) {
    u64 r; asm("fma.rn.f32x2 %0, %1, %2, %3;" : "=l"(r) : "l"(a), "l"(b), "l"(c)); return r;
}

// ---------------- prep kernels (assign at launch position 3 for ncu) ----------------
__global__ void prep_zero_a_kernel() {
    int i = blockIdx.x * 256 + threadIdx.x;   // 8192 -> lower half of g_dw
    ((float4*)g_dw)[i] = make_float4(0.f, 0.f, 0.f, 0.f);
    if (i < NUM_CODES) g_counts[i] = 0.0f;
}

__global__ void prep_cb_kernel(const float* __restrict__ cb) {
    int i = blockIdx.x * 256 + threadIdx.x;   // 32768 threads
    int c = i >> 11, r = i & 2047;
    int d = r >> 5, p = r & 31;
    int k0 = c * 64 + 2 * p;
    g_cbp[i] = pk2(cb[(size_t)k0 * 64 + d], cb[(size_t)(k0 + 1) * 64 + d]);
    if (i < NUM_CODES) {
        float s = 0.0f;
        const float4* cr = (const float4*)(cb + (size_t)i * 64);
#pragma unroll
        for (int j = 0; j < 16; j++) {
            float4 w = cr[j];
            s += w.x * w.x + w.y * w.y + w.z * w.z + w.w * w.w;
        }
        g_cnorm[i] = s;
    }
}

__global__ void prep_zero_b_kernel() {
    int i = blockIdx.x * 256 + threadIdx.x;   // 8192 -> upper half of g_dw
    ((float4*)g_dw)[8192 + i] = make_float4(0.f, 0.f, 0.f, 0.f);
    if (i == 0) g_loss = 0.0f;
}

// ---------------- assign: exact f32x2 register-tiled distance GEMM ----------------
// 256 threads, 128 tokens/CTA, 1024 CTAs. cg = tid&7 (8 codes), tg = tid>>3 (4 tokens).
// 16 chunks of 64 codes. Thread tile: 4 tokens x 8 codes = 16 f32x2 accumulators.
__global__ void __launch_bounds__(256, 2)
assign_kernel(const float4* __restrict__ z4, const float4* __restrict__ cb4,
              float* __restrict__ out) {
    extern __shared__ __align__(16) char smem[];
    float* cns   = (float*)(smem + SM_CNS);
    int*   sidx  = (int*)(smem + SM_SIDX);
    float* sbest = (float*)(smem + SM_SBEST);

    const int tid  = threadIdx.x;
    const int cg   = tid & 7;
    const int tg   = tid >> 3;
    const int base = blockIdx.x * 128;

    // ---- stage z, duplicated pairs: zdup[d][t] = (z[t][d], z[t][d]), row stride 1040B
#pragma unroll
    for (int i = 0; i < 8; i++) {
        int l = tid + i * 256;               // 2048 float4
        int t = l >> 4, j = l & 15;
        float4 v = z4[(size_t)(base + t) * 16 + j];
        *(u64*)(smem + SM_Z + (4 * j + 0) * ZSTRIDE + t * 8) = pk2(v.x, v.x);
        *(u64*)(smem + SM_Z + (4 * j + 1) * ZSTRIDE + t * 8) = pk2(v.y, v.y);
        *(u64*)(smem + SM_Z + (4 * j + 2) * ZSTRIDE + t * 8) = pk2(v.z, v.z);
        *(u64*)(smem + SM_Z + (4 * j + 3) * ZSTRIDE + t * 8) = pk2(v.w, v.w);
    }
    // ---- resident code norms
#pragma unroll
    for (int i = 0; i < 4; i++) cns[tid + i * 256] = g_cnorm[tid + i * 256];

    // ---- prefetch chunk 0 code pairs
    u64 pf[8];
#pragma unroll
    for (int i = 0; i < 8; i++) pf[i] = g_cbp[tid + i * 256];

    float best[4];
    int   bidx[4];
#pragma unroll
    for (int t = 0; t < 4; t++) { best[t] = 3.0e38f; bidx[t] = 0; }
    const u64 NEG2 = pk2(-2.0f, -2.0f);

    for (int c = 0; c < 16; c++) {
        __syncthreads();   // previous chunk's readers done
        // store code pairs: slot(d,p) = d*272 + p*8 + (p>>4)*16
#pragma unroll
        for (int i = 0; i < 8; i++) {
            int l = tid + i * 256;
            int d = l >> 5, p = l & 31;
            *(u64*)(smem + SM_C + d * 272 + p * 8 + ((p >> 4) << 4)) = pf[i];
        }
        __syncthreads();   // tile ready
        if (c < 15) {
#pragma unroll
            for (int i = 0; i < 8; i++)
                pf[i] = g_cbp[(c + 1) * 2048 + tid + i * 256];
        }

        u64 acc[16];
#pragma unroll
        for (int i = 0; i < 16; i++) acc[i] = 0ull;

#pragma unroll 16
        for (int d = 0; d < 64; d++) {
            const char* zr = smem + SM_Z + d * ZSTRIDE + tg * 32;
            ulonglong2 za = *(const ulonglong2*)zr;
            ulonglong2 zb = *(const ulonglong2*)(zr + 16);
            const char* cr = smem + SM_C + d * 272 + cg * 32 + ((cg & 4) << 2);
            ulonglong2 ca = *(const ulonglong2*)cr;
            ulonglong2 cb2 = *(const ulonglong2*)(cr + 16);
            u64 zz0 = za.x, zz1 = za.y, zz2 = zb.x, zz3 = zb.y;
            u64 cc0 = ca.x, cc1 = ca.y, cc2 = cb2.x, cc3 = cb2.y;
            acc[0]  = fma2(zz0, cc0, acc[0]);
            acc[1]  = fma2(zz0, cc1, acc[1]);
            acc[2]  = fma2(zz0, cc2, acc[2]);
            acc[3]  = fma2(zz0, cc3, acc[3]);
            acc[4]  = fma2(zz1, cc0, acc[4]);
            acc[5]  = fma2(zz1, cc1, acc[5]);
            acc[6]  = fma2(zz1, cc2, acc[6]);
            acc[7]  = fma2(zz1, cc3, acc[7]);
            acc[8]  = fma2(zz2, cc0, acc[8]);
            acc[9]  = fma2(zz2, cc1, acc[9]);
            acc[10] = fma2(zz2, cc2, acc[10]);
            acc[11] = fma2(zz2, cc3, acc[11]);
            acc[12] = fma2(zz3, cc0, acc[12]);
            acc[13] = fma2(zz3, cc1, acc[13]);
            acc[14] = fma2(zz3, cc2, acc[14]);
            acc[15] = fma2(zz3, cc3, acc[15]);
        }

        // ---- epilogue: score pair = cn - 2*dot, running argmin (ascending index)
        const int kb = c * 64;
#pragma unroll
        for (int q = 0; q < 4; q++) {
            u64 cnp = *(const u64*)&cns[kb + cg * 8 + 2 * q];
            int idx0 = kb + cg * 8 + 2 * q;
#pragma unroll
            for (int t = 0; t < 4; t++) {
                u64 sp = fma2(acc[t * 4 + q], NEG2, cnp);
                float s0, s1;
                upk2(sp, s0, s1);
                if (s0 < best[t]) { best[t] = s0; bidx[t] = idx0; }
                if (s1 < best[t]) { best[t] = s1; bidx[t] = idx0 + 1; }
            }
        }
    }

    // ---- cross-lane argmin over 8 cg (lane bits 0..2), tie-break lowest index
#pragma unroll
    for (int t = 0; t < 4; t++) {
        float v = best[t];
        int   i = bidx[t];
#pragma unroll
        for (int off = 1; off <= 4; off <<= 1) {
            float ov = __shfl_xor_sync(0xffffffffu, v, off);
            int   oi = __shfl_xor_sync(0xffffffffu, i, off);
            if (ov < v || (ov == v && oi < i)) { v = ov; i = oi; }
        }
        if (cg == 0) { sidx[tg * 4 + t] = i; sbest[tg * 4 + t] = v; }
    }
    __syncthreads();

    // ---- scatter: 2 threads per token (halves of the 64 dims)
    {
        int tl = tid >> 1, half = tid & 1;
        int idx = sidx[tl];
        int tok = base + tl;
        float zn = 0.0f;
        float* dwp = &g_dw[idx * 64 + half * 32];
#pragma unroll
        for (int d = 0; d < 32; d++) {
            int dd = half * 32 + d;
            float zv = *(const float*)(smem + SM_Z + dd * ZSTRIDE + tl * 8);
            zn += zv * zv;
            atomicAdd(&dwp[d], zv);
        }
        if (half == 0) {
            out[OUT_IDX + tok] = (float)idx;
            atomicAdd(&g_counts[idx], 1.0f);
            zn += sbest[tl];     // exact d2min contribution
        }
#pragma unroll
        for (int off = 16; off > 0; off >>= 1)
            zn += __shfl_down_sync(0xffffffffu, zn, off);
        if ((tid & 31) == 0) atomicAdd(&g_loss, zn);
    }

    // ---- quantized: cooperative coalesced gather (sidx already synced)
    float4* outq = (float4*)out;   // OUT_Q == 0
#pragma unroll
    for (int i = 0; i < 8; i++) {
        int l = tid + i * 256;
        int t = l >> 4, j = l & 15;
        outq[(size_t)(base + t) * 16 + j] = cb4[(size_t)sidx[t] * 16 + j];
    }
}

// ---------------- finalize A: per-code stats + loss ----------------
__global__ void finalize_a_kernel(const float* __restrict__ cs_in,
                                  float* __restrict__ out) {
    __shared__ float s[1024];
    int k = threadIdx.x;
    float ncs = DECAY * cs_in[k] + OMD * g_counts[k];
    s[k] = ncs;
    __syncthreads();
    for (int st = 512; st > 0; st >>= 1) {
        if (k < st) s[k] += s[k + st];
        __syncthreads();
    }
    float n   = s[0];
    float csk = (ncs + EPS) / (n + NUM_CODES * EPS) * n;
    out[OUT_CS + k] = ncs;
    g_inv[k] = 1.0f / csk;
    if (k == 0) out[OUT_LOSS] = g_loss * (1.0f / (float)(N_TOKENS * CODE_DIM));
}

// ---------------- finalize B: parallel EMA + codebook update ----------------
__global__ void finalize_b_kernel(const float* __restrict__ ema_in,
                                  float* __restrict__ out) {
    int i = blockIdx.x * 256 + threadIdx.x;   // 65536 threads
    float e = DECAY * ema_in[i] + OMD * g_dw[i];
    out[OUT_EMA + i] = e;
    out[OUT_CB + i]  = e * g_inv[i >> 6];
}

extern "C" void kernel_launch(void* const* d_in, const int* in_sizes, int n_in,
                              void* d_out, int out_size) {
    const float* z   = (const float*)d_in[0];
    const float* cb  = (const float*)d_in[1];
    const float* cs  = (const float*)d_in[2];
    const float* ema = (const float*)d_in[3];
    float* out = (float*)d_out;

    static int smem_set = 0;
    if (!smem_set) {
        cudaFuncSetAttribute(assign_kernel,
                             cudaFuncAttributeMaxDynamicSharedMemorySize, SMEM_BYTES);
        smem_set = 1;
    }

    prep_zero_a_kernel<<<32, 256>>>();                                   // pos 0
    prep_cb_kernel<<<128, 256>>>(cb);                                    // pos 1
    prep_zero_b_kernel<<<32, 256>>>();                                   // pos 2
    assign_kernel<<<1024, 256, SMEM_BYTES>>>((const float4*)z,           // pos 3
                                             (const float4*)cb, out);
    finalize_a_kernel<<<1, 1024>>>(cs, out);                             // pos 4
    finalize_b_kernel<<<256, 256>>>(ema, out);                           // pos 5
}

// round 10
// speedup vs baseline: 3.2868x; 1.9999x over previous
#include <cuda_runtime.h>
#include <cstdint>

typedef unsigned long long u64;

#define N_TOKENS  131072
#define NUM_CODES 1024
#define CODE_DIM  64
#define DECAY     0.99f
#define OMD       0.01f
#define EPS       1e-5f

#define OUT_Q     0
#define OUT_IDX   (N_TOKENS * CODE_DIM)
#define OUT_LOSS  (OUT_IDX + N_TOKENS)
#define OUT_CB    (OUT_LOSS + 1)
#define OUT_CS    (OUT_CB + NUM_CODES * CODE_DIM)
#define OUT_EMA   (OUT_CS + NUM_CODES)

// smem layout (bytes)
#define SM_ZS     0                 // 64 d-rows x 128 tokens x 4B = 32768 (plain f32)
#define SM_C0     32768             // code tile buf0: 64 x 272 = 17408
#define SM_C1     50176             // code tile buf1: 17408
#define SM_CNS    67584             // 1024 floats = 4096
#define SM_SIDX   71680             // 128 int
#define SM_SBEST  72192             // 128 float
#define SMEM_BYTES 72704

// ---------------- device scratch ----------------
__device__ __align__(16) u64 g_cbp[16 * 64 * 32];  // [chunk][dim][pair] packed code pairs
__device__ float g_dw[NUM_CODES * CODE_DIM];
__device__ float g_counts[NUM_CODES];
__device__ float g_cnorm[NUM_CODES];
__device__ float g_inv[NUM_CODES];
__device__ float g_loss;

// ---------------- helpers ----------------
__device__ __forceinline__ uint32_t smem_u32(const void* p) {
    uint32_t a;
    asm("{ .reg .u64 t; cvta.to.shared.u64 t, %1; cvt.u32.u64 %0, t; }" : "=r"(a) : "l"(p));
    return a;
}
__device__ __forceinline__ u64 pk2(float x, float y) {
    u64 r; asm("mov.b64 %0, {%1, %2};" : "=l"(r) : "f"(x), "f"(y)); return r;
}
__device__ __forceinline__ void upk2(u64 v, float& x, float& y) {
    asm("mov.b64 {%0, %1}, %2;" : "=f"(x), "=f"(y) : "l"(v));
}
__device__ __forceinline__ u64 fma2(u64 a, u64 b, u64 c) {
    u64 r; asm("fma.rn.f32x2 %0, %1, %2, %3;" : "=l"(r) : "l"(a), "l"(b), "l"(c)); return r;
}
__device__ __forceinline__ void cpa16(uint32_t dst, const void* src) {
    asm volatile("cp.async.cg.shared.global [%0], [%1], 16;" :: "r"(dst), "l"(src));
}
#define CP_COMMIT() asm volatile("cp.async.commit_group;" ::: "memory")
#define CP_WAIT1()  asm volatile("cp.async.wait_group 1;" ::: "memory")
#define CP_WAIT0()  asm volatile("cp.async.wait_group 0;" ::: "memory")

// ---------------- prep kernels (assign at launch position 3 for ncu) ----------------
__global__ void prep_zero_a_kernel() {
    int i = blockIdx.x * 256 + threadIdx.x;   // 8192 -> lower half of g_dw
    ((float4*)g_dw)[i] = make_float4(0.f, 0.f, 0.f, 0.f);
    if (i < NUM_CODES) g_counts[i] = 0.0f;
}

__global__ void prep_cb_kernel(const float* __restrict__ cb) {
    int i = blockIdx.x * 256 + threadIdx.x;   // 32768 threads
    int c = i >> 11, r = i & 2047;
    int d = r >> 5, p = r & 31;
    int k0 = c * 64 + 2 * p;
    g_cbp[i] = pk2(cb[(size_t)k0 * 64 + d], cb[(size_t)(k0 + 1) * 64 + d]);
    if (i < NUM_CODES) {
        float s = 0.0f;
        const float4* cr = (const float4*)(cb + (size_t)i * 64);
#pragma unroll
        for (int j = 0; j < 16; j++) {
            float4 w = cr[j];
            s += w.x * w.x + w.y * w.y + w.z * w.z + w.w * w.w;
        }
        g_cnorm[i] = s;
    }
}

__global__ void prep_zero_b_kernel() {
    int i = blockIdx.x * 256 + threadIdx.x;   // 8192 -> upper half of g_dw
    ((float4*)g_dw)[8192 + i] = make_float4(0.f, 0.f, 0.f, 0.f);
    if (i == 0) g_loss = 0.0f;
}

// ---------------- assign: exact f32x2 GEMM, 8 tokens x 8 codes per thread ----------------
// 128 threads, 128 tokens/CTA, 1024 CTAs. cg = tid&7 (8 codes), tgrp = tid>>3 (8 tokens).
// z scalar-broadcast LDS.32 + in-register dup; code tiles double-buffered via cp.async.
__global__ void __launch_bounds__(128, 3)
assign_kernel(const float4* __restrict__ z4, const float4* __restrict__ cb4,
              float* __restrict__ out) {
    extern __shared__ __align__(16) char smem[];
    float* cns   = (float*)(smem + SM_CNS);
    int*   sidx  = (int*)(smem + SM_SIDX);
    float* sbest = (float*)(smem + SM_SBEST);

    const int tid  = threadIdx.x;
    const int cg   = tid & 7;
    const int tgrp = tid >> 3;           // 0..15, owns tokens tgrp*8..tgrp*8+7
    const int base = blockIdx.x * 128;
    const uint32_t sbase = smem_u32(smem);

    // ---- stage z: thread owns token tid; zs[d][t] plain f32 (512B rows)
    {
        const float4* zsrc = z4 + (size_t)(base + tid) * 16;
#pragma unroll
        for (int j = 0; j < 16; j++) {
            float4 v = zsrc[j];
            *(float*)(smem + SM_ZS + (4 * j + 0) * 512 + tid * 4) = v.x;
            *(float*)(smem + SM_ZS + (4 * j + 1) * 512 + tid * 4) = v.y;
            *(float*)(smem + SM_ZS + (4 * j + 2) * 512 + tid * 4) = v.z;
            *(float*)(smem + SM_ZS + (4 * j + 3) * 512 + tid * 4) = v.w;
        }
    }
    // ---- resident code norms
#pragma unroll
    for (int i = 0; i < 8; i++) cns[tid + i * 128] = g_cnorm[tid + i * 128];

    // ---- cp.async prologue: chunk 0 -> buf0
    {
        const char* src = (const char*)g_cbp;
#pragma unroll
        for (int i = 0; i < 8; i++) {
            int l = tid + i * 128;
            int d = l >> 4, p = (l & 15) * 2;
            cpa16(sbase + SM_C0 + d * 272 + p * 8 + ((p >> 4) << 4), src + (size_t)l * 16);
        }
        CP_COMMIT();
    }

    float best[8];
    int   bidx[8];
#pragma unroll
    for (int t = 0; t < 8; t++) { best[t] = 3.0e38f; bidx[t] = 0; }
    const u64 NEG2 = pk2(-2.0f, -2.0f);

    for (int c = 0; c < 16; c++) {
        __syncthreads();   // prior compute done (frees the buffer we're about to fill)
        if (c < 15) {
            const char* src = (const char*)(g_cbp + (size_t)(c + 1) * 2048);
            uint32_t boff = ((c + 1) & 1) ? SM_C1 : SM_C0;
#pragma unroll
            for (int i = 0; i < 8; i++) {
                int l = tid + i * 128;
                int d = l >> 4, p = (l & 15) * 2;
                cpa16(sbase + boff + d * 272 + p * 8 + ((p >> 4) << 4), src + (size_t)l * 16);
            }
            CP_COMMIT();
            CP_WAIT1();    // chunk c's group complete
        } else {
            CP_WAIT0();
        }
        __syncthreads();   // chunk c visible to all

        const char* cbuf = smem + ((c & 1) ? SM_C1 : SM_C0);

        u64 acc[32];
#pragma unroll
        for (int i = 0; i < 32; i++) acc[i] = 0ull;

#pragma unroll 8
        for (int d = 0; d < 64; d++) {
            u64 zz[8];
#pragma unroll
            for (int t = 0; t < 8; t++) {
                float zv = *(const float*)(smem + SM_ZS + d * 512 + (tgrp * 8 + t) * 4);
                zz[t] = pk2(zv, zv);
            }
            const char* cr = cbuf + d * 272 + cg * 32 + ((cg & 4) << 2);
            ulonglong2 ca  = *(const ulonglong2*)cr;
            ulonglong2 cb2 = *(const ulonglong2*)(cr + 16);
            u64 cc0 = ca.x, cc1 = ca.y, cc2 = cb2.x, cc3 = cb2.y;
#pragma unroll
            for (int t = 0; t < 8; t++) {
                acc[t * 4 + 0] = fma2(zz[t], cc0, acc[t * 4 + 0]);
                acc[t * 4 + 1] = fma2(zz[t], cc1, acc[t * 4 + 1]);
                acc[t * 4 + 2] = fma2(zz[t], cc2, acc[t * 4 + 2]);
                acc[t * 4 + 3] = fma2(zz[t], cc3, acc[t * 4 + 3]);
            }
        }

        // ---- epilogue: score pair = cn - 2*dot, running argmin
        const int kb = c * 64;
#pragma unroll
        for (int q = 0; q < 4; q++) {
            u64 cnp = *(const u64*)&cns[kb + cg * 8 + 2 * q];
            int idx0 = kb + cg * 8 + 2 * q;
#pragma unroll
            for (int t = 0; t < 8; t++) {
                u64 sp = fma2(acc[t * 4 + q], NEG2, cnp);
                float s0, s1;
                upk2(sp, s0, s1);
                if (s0 < best[t]) { best[t] = s0; bidx[t] = idx0; }
                if (s1 < best[t]) { best[t] = s1; bidx[t] = idx0 + 1; }
            }
        }
    }

    // ---- cross-lane argmin over 8 cg lanes (lane bits 0..2), tie-break lowest index
#pragma unroll
    for (int t = 0; t < 8; t++) {
        float v = best[t];
        int   i = bidx[t];
#pragma unroll
        for (int off = 1; off <= 4; off <<= 1) {
            float ov = __shfl_xor_sync(0xffffffffu, v, off);
            int   oi = __shfl_xor_sync(0xffffffffu, i, off);
            if (ov < v || (ov == v && oi < i)) { v = ov; i = oi; }
        }
        if (cg == 0) { sidx[tgrp * 8 + t] = i; sbest[tgrp * 8 + t] = v; }
    }
    __syncthreads();

    // ---- scatter: thread owns token tid (z read from smem, conflict-free banks)
    {
        int idx = sidx[tid];
        int tok = base + tid;
        out[OUT_IDX + tok] = (float)idx;
        atomicAdd(&g_counts[idx], 1.0f);
        float zn = 0.0f;
        float* dwp = &g_dw[idx * 64];
#pragma unroll 8
        for (int d = 0; d < 64; d++) {
            float zv = *(const float*)(smem + SM_ZS + d * 512 + tid * 4);
            zn += zv * zv;
            atomicAdd(&dwp[d], zv);
        }
        float lp = zn + sbest[tid];   // exact d2min
#pragma unroll
        for (int off = 16; off > 0; off >>= 1)
            lp += __shfl_down_sync(0xffffffffu, lp, off);
        if ((tid & 31) == 0) atomicAdd(&g_loss, lp);
    }

    // ---- quantized: cooperative coalesced gather
    float4* outq = (float4*)out;   // OUT_Q == 0
#pragma unroll
    for (int i = 0; i < 16; i++) {
        int l = tid + i * 128;
        int t = l >> 4, j = l & 15;
        outq[(size_t)(base + t) * 16 + j] = cb4[(size_t)sidx[t] * 16 + j];
    }
}

// ---------------- finalize A: per-code stats + loss ----------------
__global__ void finalize_a_kernel(const float* __restrict__ cs_in,
                                  float* __restrict__ out) {
    __shared__ float s[1024];
    int k = threadIdx.x;
    float ncs = DECAY * cs_in[k] + OMD * g_counts[k];
    s[k] = ncs;
    __syncthreads();
    for (int st = 512; st > 0; st >>= 1) {
        if (k < st) s[k] += s[k + st];
        __syncthreads();
    }
    float n   = s[0];
    float csk = (ncs + EPS) / (n + NUM_CODES * EPS) * n;
    out[OUT_CS + k] = ncs;
    g_inv[k] = 1.0f / csk;
    if (k == 0) out[OUT_LOSS] = g_loss * (1.0f / (float)(N_TOKENS * CODE_DIM));
}

// ---------------- finalize B: parallel EMA + codebook update ----------------
__global__ void finalize_b_kernel(const float* __restrict__ ema_in,
                                  float* __restrict__ out) {
    int i = blockIdx.x * 256 + threadIdx.x;   // 65536 threads
    float e = DECAY * ema_in[i] + OMD * g_dw[i];
    out[OUT_EMA + i] = e;
    out[OUT_CB + i]  = e * g_inv[i >> 6];
}

extern "C" void kernel_launch(void* const* d_in, const int* in_sizes, int n_in,
                              void* d_out, int out_size) {
    const float* z   = (const float*)d_in[0];
    const float* cb  = (const float*)d_in[1];
    const float* cs  = (const float*)d_in[2];
    const float* ema = (const float*)d_in[3];
    float* out = (float*)d_out;

    static int smem_set = 0;
    if (!smem_set) {
        cudaFuncSetAttribute(assign_kernel,
                             cudaFuncAttributeMaxDynamicSharedMemorySize, SMEM_BYTES);
        smem_set = 1;
    }

    prep_zero_a_kernel<<<32, 256>>>();                                   // pos 0
    prep_cb_kernel<<<128, 256>>>(cb);                                    // pos 1
    prep_zero_b_kernel<<<32, 256>>>();                                   // pos 2
    assign_kernel<<<1024, 128, SMEM_BYTES>>>((const float4*)z,           // pos 3
                                             (const float4*)cb, out);
    finalize_a_kernel<<<1, 1024>>>(cs, out);                             // pos 4
    finalize_b_kernel<<<256, 256>>>(ema, out);                           // pos 5
}